// round 14
// baseline (speedup 1.0000x reference)
#include <cuda_runtime.h>
#include <math.h>

__device__ float g_feats[4096 * 64];
__device__ float g_lors[512 * 24 * 64];
__device__ float g_U[2 * 16 * 32 * 32];
__device__ float g_tagw[4 * 64];
__device__ float g_ploss[512];
__device__ float g_pcorr[512];

__device__ __forceinline__ float gelu_f(float x) {
    return 0.5f * x * (1.0f + erff(x * 0.70710678118654752f));
}

__global__ void dummy_kernel() {}

// ============ precompute tagw[tg][e] = sum_d w1[e][d] * tags[tg][d] ============
__global__ void prep_kernel(const float* __restrict__ w1, const float* __restrict__ tags)
{
    int id = threadIdx.x;          // 256 threads
    int tg = id >> 6;
    int e = id & 63;
    float s = 0.f;
    for (int d = 0; d < 64; d++) s = fmaf(w1[e * 64 + d], tags[tg * 64 + d], s);
    g_tagw[tg * 64 + e] = s;
}

// ============ transformed conv weights: U = G g G^T, per layer ============
// stored interleaved for float4 GEMM loads: slot j*4+k holds co = k*8+j
__global__ void wtrans_kernel(const float* __restrict__ c2w, const float* __restrict__ c3w)
{
    int L = blockIdx.x;
    const float* wsrc = L ? c3w : c2w;
    for (int id = threadIdx.x; id < 1024; id += 256) {
        int ci = id & 31;
        int co = id >> 5;
        int slot = (co & 7) * 4 + (co >> 3);
        const float* g = wsrc + (co * 32 + ci) * 9;
        float tr[4][3];
        for (int j = 0; j < 3; j++) {
            float g0 = g[j], g1 = g[3 + j], g2 = g[6 + j];
            tr[0][j] = g0;
            tr[1][j] = 0.5f * (g0 + g1 + g2);
            tr[2][j] = 0.5f * (g0 - g1 + g2);
            tr[3][j] = g2;
        }
        for (int i = 0; i < 4; i++) {
            float t0 = tr[i][0], t1 = tr[i][1], t2 = tr[i][2];
            float u0 = t0;
            float u1 = 0.5f * (t0 + t1 + t2);
            float u2 = 0.5f * (t0 - t1 + t2);
            float u3 = t2;
            int base = ((L * 16 + i * 4) * 32 + ci) * 32 + slot;
            g_U[base]            = u0;
            g_U[base + 1 * 1024] = u1;
            g_U[base + 2 * 1024] = u2;
            g_U[base + 3 * 1024] = u3;
        }
    }
}

// ============ feature extractor: 1 image/block, 512 threads ============
__global__ __launch_bounds__(512, 2) void feat_kernel(
    const float* __restrict__ sxs, const float* __restrict__ qxs,
    const float* __restrict__ c1w, const float* __restrict__ c1b, const float* __restrict__ bn1,
    const float* __restrict__ c2b, const float* __restrict__ bn2,
    const float* __restrict__ c3b, const float* __restrict__ bn3,
    const float* __restrict__ c4w, const float* __restrict__ c4b, const float* __restrict__ bn4,
    const float* __restrict__ lin_w)
{
    extern __shared__ float sm[];
    float* Vs   = sm;           // 8192 (V, also conv1 scratch)
    float* bufA = sm + 8192;    // 3300
    float* bufB = sm + 11492;   // 3300
    float* w1s  = sm + 14792;   // 288
    float* w4s  = sm + 15080;   // 288
    float* A1 = sm + 15368; float* B1 = sm + 15400;
    float* A2 = sm + 15432; float* B2 = sm + 15464;
    float* A3 = sm + 15496; float* B3 = sm + 15528;
    float* AB4 = sm + 15560;
    float* flat = sm + 15568;
    float* red = sm + 15632;
    float* Ms = sm + 16144;     // 8704
    // total 24848 floats

    const int t = threadIdx.x;
    const int c = t & 31;
    const int g16 = t >> 5;
    const int img = blockIdx.x;
    const float* src = (img < 3072) ? (sxs + img * 784) : (qxs + (img - 3072) * 784);

    for (int i = t; i < 288; i += 512) {
        int co = i / 9; int k = i - co * 9;
        w1s[k * 32 + co] = c1w[i];
        w4s[i] = c4w[i];
    }
    if (t < 32) {
        float g = bn1[t], bt = bn1[32 + t], m = bn1[64 + t], v = bn1[96 + t];
        float sc = g * rsqrtf(v + 1e-5f);
        A1[t] = sc * 0.0625f;
        B1[t] = (c1b[t] - m) * sc + bt;
        g = bn2[t]; bt = bn2[32 + t]; m = bn2[64 + t]; v = bn2[96 + t];
        sc = g * rsqrtf(v + 1e-5f);
        A2[t] = sc; B2[t] = (c2b[t] - m) * sc + bt;
        g = bn3[t]; bt = bn3[32 + t]; m = bn3[64 + t]; v = bn3[96 + t];
        sc = g * rsqrtf(v + 1e-5f);
        A3[t] = sc; B3[t] = (c3b[t] - m) * sc + bt;
    }
    if (t == 0) {
        float g = bn4[0], bt = bn4[1], m = bn4[2], v = bn4[3];
        float sc = g * rsqrtf(v + 1e-5f);
        AB4[0] = sc; AB4[1] = (c4b[0] - m) * sc + bt;
    }
    for (int i = t; i < 3300; i += 512) { bufA[i] = 0.f; bufB[i] = 0.f; }

    float* inpad = Vs;
    float* rs4 = Vs + 1024;
    float* Ws = Vs + 2048;
    for (int i = t; i < 900; i += 512) {
        int yy = i / 30; int xx = i - yy * 30;
        float v = 0.f;
        if (yy >= 1 && yy <= 28 && xx >= 1 && xx <= 28) v = src[(yy - 1) * 28 + xx - 1];
        inpad[i] = v;
    }
    __syncthreads();
    {
        const int SO[8] = {0, 3, 7, 10, 14, 17, 21, 24};
        for (int i = t; i < 720; i += 512) {
            int u = i / 24; int b3 = i - u * 24;
            int b = SO[b3 / 3] + (b3 % 3);
            const float* ip = inpad + u * 30 + b;
            rs4[i] = ip[0] + ip[1] + ip[2] + ip[3];
        }
        __syncthreads();
        for (int i = t; i < 576; i += 512) {
            int a3 = i / 24; int b3 = i - a3 * 24;
            int a = SO[a3 / 3] + (a3 % 3);
            Ws[i] = rs4[a * 24 + b3] + rs4[(a + 1) * 24 + b3] + rs4[(a + 2) * 24 + b3] + rs4[(a + 3) * 24 + b3];
        }
        __syncthreads();
        int y = g16 >> 1;
        int x0 = (g16 & 1) * 4;
        float acc[4];
        for (int x = 0; x < 4; x++) acc[x] = 0.f;
        for (int dy = 0; dy < 3; dy++) for (int dx = 0; dx < 3; dx++) {
            float wv = w1s[(dy * 3 + dx) * 32 + c];
            for (int x = 0; x < 4; x++) acc[x] = fmaf(wv, Ws[(3 * y + dy) * 24 + 3 * (x0 + x) + dx], acc[x]);
        }
        float a1 = A1[c], b1 = B1[c];
        for (int x = 0; x < 4; x++) bufA[((y + 1) * 10 + x0 + x + 1) * 33 + c] = gelu_f(acc[x] * a1 + b1);
    }
    __syncthreads();

    for (int L = 0; L < 2; L++) {
        const float* inb = L ? bufB : bufA;
        float* outb = L ? bufA : bufB;
        const float* Asc = L ? A3 : A2;
        const float* Bof = L ? B3 : B2;

        {
            int tl = t & 15; int ci = t >> 4;
            int ty = tl >> 2; int tx = tl & 3;
            const float* base = inb + (2 * ty * 10 + 2 * tx) * 33 + ci;
            float d[4][4];
            for (int r = 0; r < 4; r++) for (int cc = 0; cc < 4; cc++) d[r][cc] = base[(r * 10 + cc) * 33];
            float tm[4][4];
            for (int j = 0; j < 4; j++) {
                tm[0][j] = d[0][j] - d[2][j];
                tm[1][j] = d[1][j] + d[2][j];
                tm[2][j] = d[2][j] - d[1][j];
                tm[3][j] = d[1][j] - d[3][j];
            }
            for (int i = 0; i < 4; i++) {
                Vs[(i * 4 + 0) * 512 + ci * 16 + tl] = tm[i][0] - tm[i][2];
                Vs[(i * 4 + 1) * 512 + ci * 16 + tl] = tm[i][1] + tm[i][2];
                Vs[(i * 4 + 2) * 512 + ci * 16 + tl] = tm[i][2] - tm[i][1];
                Vs[(i * 4 + 3) * 512 + ci * 16 + tl] = tm[i][1] - tm[i][3];
            }
        }
        __syncthreads();

        {
            int uv = g16;
            int q = c >> 3;
            int j = c & 7;
            float acc[16];
            for (int i = 0; i < 16; i++) acc[i] = 0.f;
            const float4* V4 = (const float4*)(Vs + uv * 512) + q;
            const float4* U4 = (const float4*)(g_U + (L * 16 + uv) * 1024) + j;
            #pragma unroll 8
            for (int ci = 0; ci < 32; ci++) {
                float4 v = V4[ci * 4];
                float4 u = U4[ci * 8];
                acc[0]  = fmaf(v.x, u.x, acc[0]);
                acc[1]  = fmaf(v.x, u.y, acc[1]);
                acc[2]  = fmaf(v.x, u.z, acc[2]);
                acc[3]  = fmaf(v.x, u.w, acc[3]);
                acc[4]  = fmaf(v.y, u.x, acc[4]);
                acc[5]  = fmaf(v.y, u.y, acc[5]);
                acc[6]  = fmaf(v.y, u.z, acc[6]);
                acc[7]  = fmaf(v.y, u.w, acc[7]);
                acc[8]  = fmaf(v.z, u.x, acc[8]);
                acc[9]  = fmaf(v.z, u.y, acc[9]);
                acc[10] = fmaf(v.z, u.z, acc[10]);
                acc[11] = fmaf(v.z, u.w, acc[11]);
                acc[12] = fmaf(v.w, u.x, acc[12]);
                acc[13] = fmaf(v.w, u.y, acc[13]);
                acc[14] = fmaf(v.w, u.z, acc[14]);
                acc[15] = fmaf(v.w, u.w, acc[15]);
            }
            float* Mw = Ms + uv * 544 + (q * 4) * 34 + j;
            for (int tlk = 0; tlk < 4; tlk++)
                for (int k = 0; k < 4; k++)
                    Mw[tlk * 34 + k * 8] = acc[tlk * 4 + k];
        }
        __syncthreads();

        {
            int co2 = t & 31; int tl = t >> 5;
            int ty = tl >> 2; int tx = tl & 3;
            float M[4][4];
            for (int i = 0; i < 4; i++) for (int j = 0; j < 4; j++) M[i][j] = Ms[(i * 4 + j) * 544 + tl * 34 + co2];
            float t0[2][4];
            for (int j = 0; j < 4; j++) {
                t0[0][j] = M[0][j] + M[1][j] + M[2][j];
                t0[1][j] = M[1][j] - M[2][j] - M[3][j];
            }
            float a = Asc[co2], bo = Bof[co2];
            for (int i = 0; i < 2; i++) {
                float y0 = t0[i][0] + t0[i][1] + t0[i][2];
                float y1 = t0[i][1] - t0[i][2] - t0[i][3];
                int rr = 1 + 2 * ty + i;
                int cc0 = 1 + 2 * tx;
                outb[(rr * 10 + cc0) * 33 + co2] = gelu_f(y0 * a + bo);
                outb[(rr * 10 + cc0 + 1) * 33 + co2] = gelu_f(y1 * a + bo);
            }
        }
        __syncthreads();
    }

    {
        int y = g16 >> 1;
        int x0 = (g16 & 1) * 4;
        float acc[4];
        for (int x = 0; x < 4; x++) acc[x] = 0.f;
        for (int dy = 0; dy < 3; dy++) for (int dx = 0; dx < 3; dx++) {
            float wv = w4s[c * 9 + dy * 3 + dx];
            const float* rp = bufA + ((y + dy) * 10 + x0 + dx) * 33 + c;
            for (int x = 0; x < 4; x++) acc[x] = fmaf(wv, rp[x * 33], acc[x]);
        }
        for (int x = 0; x < 4; x++) {
            float v = acc[x];
            for (int o = 16; o; o >>= 1) v += __shfl_xor_sync(0xffffffffu, v, o);
            if (c == 0) flat[y * 8 + x0 + x] = gelu_f(v * AB4[0] + AB4[1]);
        }
    }
    __syncthreads();

    {
        int e = t & 63;
        int h = t >> 6;
        int j0 = h * 8;
        float p = 0.f;
        for (int jj = 0; jj < 8; jj += 4) {
            float4 lw = *(const float4*)(lin_w + e * 64 + j0 + jj);
            p = fmaf(lw.x, flat[j0 + jj], p);
            p = fmaf(lw.y, flat[j0 + jj + 1], p);
            p = fmaf(lw.z, flat[j0 + jj + 2], p);
            p = fmaf(lw.w, flat[j0 + jj + 3], p);
        }
        red[h * 64 + e] = p;
        __syncthreads();
        if (t < 64) {
            float s = 0.f;
            for (int h2 = 0; h2 < 8; h2++) s += red[h2 * 64 + t];
            g_feats[img * 64 + t] = s;
        }
    }
}

// ============ LoR adapter: 16 tokens/block x 64 threads ============
__global__ __launch_bounds__(1024) void lor_kernel(
    const float* __restrict__ emb, const float* __restrict__ w1, const float* __restrict__ w2,
    const float* __restrict__ tags, const float* __restrict__ rq, const float* __restrict__ rk,
    const float* __restrict__ rv, const float* __restrict__ ro,
    const float* __restrict__ lnw, const float* __restrict__ lnb, const int* __restrict__ sys)
{
    extern __shared__ float sm[];
    float* w1T = sm;
    float* w2T = sm + 4160;
    float* rqT = sm + 8320;
    float* roS = sm + 12480;
    float* rkT = sm + 16576;
    float* rvS = sm + 17600;
    float* partS = sm + 18624;   // 1024 (first-GEMV partials)
    float* ahs = sm + 19648;
    float* qvs = sm + 20672;
    float* lvs = sm + 21696;
    float* rA = sm + 22720;
    float* rB = sm + 22752;
    float* bndS = sm + 22784;    // 256
    float* tgS = sm + 23040;     // 256
    float* tgwS = sm + 23296;    // 256 -> total 23552
    const int t = threadIdx.x;
    for (int i = t; i < 4096; i += 1024) {
        int e = i >> 6; int d = i & 63;
        w1T[d * 65 + e] = w1[i];
        w2T[d * 65 + e] = w2[i];
        rqT[d * 65 + e] = rq[i];
        roS[i] = ro[i];
    }
    {
        int n = t >> 8; int h = (t >> 4) & 15; int r = t & 15;
        rkT[t] = rk[(r * 4 + n) * 16 + h];
        rvS[t] = rv[t];
    }
    if (t < 256) {
        tgS[t] = tags[t];
        tgwS[t] = g_tagw[t];
    }
    const int lt = t >> 6;
    const int j = t & 63;
    const int tok = blockIdx.x * 16 + lt;
    const int b = tok / 24;
    const int k24 = tok - b * 24;
    const int s = k24 >> 2;
    const int tg = k24 & 3;
    const int g4 = lt >> 2;      // group within block (4 tokens share bound)
    if ((lt & 3) == 0) {
        int cls = sys[b * 6 + s];
        bndS[g4 * 64 + j] = g_feats[(b * 6 + s) * 64 + j] + emb[cls * 64 + j];
    }
    __syncthreads();
    // first GEMV split: thread (lt = g4*4+p, j) does d in [p*16, p*16+16)
    {
        int p = lt & 3;
        float hp = 0.f;
        int d0 = p * 16;
        for (int dd = 0; dd < 16; dd++)
            hp = fmaf(w1T[(d0 + dd) * 65 + j], bndS[g4 * 64 + d0 + dd], hp);
        partS[t] = hp;
    }
    __syncthreads();
    float h1 = partS[(g4 * 4 + 0) * 64 + j] + partS[(g4 * 4 + 1) * 64 + j]
             + partS[(g4 * 4 + 2) * 64 + j] + partS[(g4 * 4 + 3) * 64 + j]
             + tgwS[tg * 64 + j];
    ahs[t] = gelu_f(h1);
    __syncthreads();
    float qv = 0.f;
    for (int d = 0; d < 64; d++) qv = fmaf(w2T[d * 65 + j], ahs[lt * 64 + d], qv);
    qvs[t] = qv;
    __syncthreads();
    float qh = 0.f;
    for (int d = 0; d < 64; d++) qh = fmaf(rqT[d * 65 + j], qvs[lt * 64 + d], qh);
    const int n = j >> 4;
    const int sub = j & 15;
    float scv = 0.f;
    for (int hh = 0; hh < 16; hh++) {
        float q2 = __shfl_sync(0xffffffffu, qh, hh, 16);
        scv = fmaf(q2, rkT[(n * 16 + hh) * 16 + sub], scv);
    }
    scv *= 0.25f;
    float mx = scv;
    for (int o = 8; o; o >>= 1) mx = fmaxf(mx, __shfl_xor_sync(0xffffffffu, mx, o, 16));
    float ee = expf(scv - mx);
    float ss = ee;
    for (int o = 8; o; o >>= 1) ss += __shfl_xor_sync(0xffffffffu, ss, o, 16);
    float p = ee / ss;
    float lv = 0.f;
    for (int r = 0; r < 16; r++) {
        float pr = __shfl_sync(0xffffffffu, p, r, 16);
        lv = fmaf(pr, rvS[(r * 4 + n) * 16 + sub], lv);
    }
    lvs[t] = lv;
    __syncthreads();
    float ov = 0.f;
    for (int d = 0; d < 64; d++) ov = fmaf(roS[d * 64 + j], lvs[lt * 64 + d], ov);
    float z = ov + bndS[g4 * 64 + j] + tgS[tg * 64 + j];
    float sv = z;
    for (int o = 16; o; o >>= 1) sv += __shfl_xor_sync(0xffffffffu, sv, o);
    int wh = j >> 5;
    if ((j & 31) == 0) rA[lt * 2 + wh] = sv;
    __syncthreads();
    float mean = (rA[lt * 2] + rA[lt * 2 + 1]) * 0.015625f;
    float dz = z - mean;
    float v2 = dz * dz;
    for (int o = 16; o; o >>= 1) v2 += __shfl_xor_sync(0xffffffffu, v2, o);
    if ((j & 31) == 0) rB[lt * 2 + wh] = v2;
    __syncthreads();
    float var = (rB[lt * 2] + rB[lt * 2 + 1]) * 0.015625f;
    g_lors[tok * 64 + j] = dz * rsqrtf(var + 1e-5f) * lnw[j] + lnb[j];
}

// ============ query path: 1 task/block, 64 threads, grid 512 ============
__global__ __launch_bounds__(64) void query_kernel(
    const float* __restrict__ emb, const float* __restrict__ w1, const float* __restrict__ w2,
    const float* __restrict__ tags, const int* __restrict__ qys)
{
    extern __shared__ float sm[];
    float* w1T = sm;            // 4160
    float* w2T = sm + 4160;     // 4160
    float* lorS = sm + 8320;    // 1536
    float* xq = sm + 9856;      // 128
    float* ah = sm + 9984;      // 128
    float* pd = sm + 10112;     // 128
    float* d1 = sm + 10240;     // 12
    float* d2 = sm + 10252;     // 12
    float* lg = sm + 10264;     // 4
    float* ls = sm + 10268;     // 2
    float* cr = sm + 10270;     // 2 -> total 10272
    const int t = threadIdx.x;
    const int b = blockIdx.x;
    for (int i = t; i < 4096; i += 64) {
        int e = i >> 6; int d = i & 63;
        w1T[d * 65 + e] = w1[i];
        w2T[d * 65 + e] = w2[i];
    }
    for (int i = t; i < 1536; i += 64) lorS[i] = g_lors[b * 1536 + i];
    const int e = t;
    for (int q = 0; q < 2; q++) xq[q * 64 + e] = g_feats[3072 * 64 + (b * 2 + q) * 64 + e] + tags[4 * 64 + e];
    __syncthreads();
    if (e < 12) {
        int s = e >> 1; int q = e & 1;
        const float* r1 = lorS + (s * 4 + 1) * 64;
        const float* xx = xq + q * 64;
        float a = 0.f;
        for (int d = 0; d < 64; d++) a = fmaf(r1[d], xx[d], a);
        d1[e] = a;
    }
    __syncthreads();
    for (int q = 0; q < 2; q++) {
        const float* xx = xq + q * 64;
        float a = 0.f;
        for (int d = 0; d < 64; d++) a = fmaf(w1T[d * 65 + e], xx[d], a);
        for (int s = 0; s < 6; s++) a = fmaf(lorS[(s * 4) * 64 + e], d1[s * 2 + q], a);
        ah[q * 64 + e] = gelu_f(a);
    }
    __syncthreads();
    if (e < 12) {
        int s = e >> 1; int q = e & 1;
        const float* r2 = lorS + (s * 4 + 3) * 64;
        const float* aa = ah + q * 64;
        float a = 0.f;
        for (int d = 0; d < 64; d++) a = fmaf(r2[d], aa[d], a);
        d2[e] = a;
    }
    __syncthreads();
    for (int q = 0; q < 2; q++) {
        const float* aa = ah + q * 64;
        float a = 0.f;
        for (int d = 0; d < 64; d++) a = fmaf(w2T[d * 65 + e], aa[d], a);
        for (int s = 0; s < 6; s++) a = fmaf(lorS[(s * 4 + 2) * 64 + e], d2[s * 2 + q], a);
        pd[q * 64 + e] = a;
    }
    __syncthreads();
    if (e < 4) {
        int q = e >> 1; int l = e & 1;
        float a = 0.f;
        for (int d = 0; d < 64; d++) a = fmaf(emb[l * 64 + d], pd[q * 64 + d], a);
        lg[e] = a;
    }
    __syncthreads();
    if (e < 2) {
        float l0 = lg[e * 2];
        float l1 = lg[e * 2 + 1];
        int yv = qys[b * 2 + e];
        float m = fmaxf(l0, l1);
        float lse = m + logf(expf(l0 - m) + expf(l1 - m));
        ls[e] = lse - (yv ? l1 : l0);
        cr[e] = (((l1 > l0) ? 1 : 0) == yv) ? 1.f : 0.f;
    }
    __syncthreads();
    if (t == 0) {
        g_ploss[b] = ls[0] + ls[1];
        g_pcorr[b] = cr[0] + cr[1];
    }
}

__global__ void reduce_kernel(float* __restrict__ out)
{
    __shared__ float sl[128];
    __shared__ float sc[128];
    int t = threadIdx.x;
    float a = 0.f, bsum = 0.f;
    for (int k = 0; k < 4; k++) {
        a += g_ploss[t + k * 128];
        bsum += g_pcorr[t + k * 128];
    }
    sl[t] = a;
    sc[t] = bsum;
    __syncthreads();
    for (int s = 64; s; s >>= 1) {
        if (t < s) { sl[t] += sl[t + s]; sc[t] += sc[t + s]; }
        __syncthreads();
    }
    if (t == 0) {
        float loss = sl[0] * 0.0009765625f;
        out[0] = loss;
        out[1] = loss;
        out[2] = 0.f;
        out[3] = sc[0];
        out[4] = 1024.f;
    }
}

extern "C" void kernel_launch(void* const* d_in, const int* in_sizes, int n_in,
                              void* d_out, int out_size)
{
    const float* sxs = (const float*)d_in[1];
    const float* qxs = (const float*)d_in[2];
    const float* c1w = (const float*)d_in[4];
    const float* c1b = (const float*)d_in[5];
    const float* bn1 = (const float*)d_in[6];
    const float* c2w = (const float*)d_in[7];
    const float* c2b = (const float*)d_in[8];
    const float* bn2 = (const float*)d_in[9];
    const float* c3w = (const float*)d_in[10];
    const float* c3b = (const float*)d_in[11];
    const float* bn3 = (const float*)d_in[12];
    const float* c4w = (const float*)d_in[13];
    const float* c4b = (const float*)d_in[14];
    const float* bn4 = (const float*)d_in[15];
    const float* lin_w = (const float*)d_in[16];
    const float* emb = (const float*)d_in[17];
    const float* w1 = (const float*)d_in[18];
    const float* w2 = (const float*)d_in[19];
    const float* tags = (const float*)d_in[20];
    const float* rq = (const float*)d_in[21];
    const float* rk = (const float*)d_in[22];
    const float* rv = (const float*)d_in[23];
    const float* ro = (const float*)d_in[24];
    const float* lnw = (const float*)d_in[25];
    const float* lnb = (const float*)d_in[26];
    const int* sys = (const int*)d_in[27];
    const int* qys = (const int*)d_in[28];
    const size_t smF = 24848 * sizeof(float);
    const size_t smL = 23552 * sizeof(float);
    const size_t smQ = 10272 * sizeof(float);
    cudaFuncSetAttribute(feat_kernel, cudaFuncAttributeMaxDynamicSharedMemorySize, (int)smF);
    cudaFuncSetAttribute(lor_kernel, cudaFuncAttributeMaxDynamicSharedMemorySize, (int)smL);
    cudaFuncSetAttribute(query_kernel, cudaFuncAttributeMaxDynamicSharedMemorySize, (int)smQ);
    // feat_kernel stays at 0-based position 3 (ncu capture slot)
    wtrans_kernel<<<2, 256>>>(c2w, c3w);
    prep_kernel<<<1, 256>>>(w1, tags);
    dummy_kernel<<<1, 32>>>();
    feat_kernel<<<4096, 512, smF>>>(sxs, qxs, c1w, c1b, bn1, c2b, bn2, c3b, bn3, c4w, c4b, bn4, lin_w);
    lor_kernel<<<768, 1024, smL>>>(emb, w1, w2, tags, rq, rk, rv, ro, lnw, lnb, sys);
    query_kernel<<<512, 64, smQ>>>(emb, w1, w2, tags, qys);
    reduce_kernel<<<1, 128>>>((float*)d_out);
}

// round 15
// speedup vs baseline: 1.0590x; 1.0590x over previous
#include <cuda_runtime.h>
#include <math.h>

__device__ float g_feats[4096 * 64];
__device__ float g_lors[512 * 24 * 64];
__device__ float g_U[2 * 16 * 32 * 32];
__device__ float g_tagw[4 * 64];
__device__ float g_ploss[128];
__device__ float g_pcorr[128];

__device__ __forceinline__ float gelu_f(float x) {
    return 0.5f * x * (1.0f + erff(x * 0.70710678118654752f));
}

// ============ precompute tagw[tg][e] = sum_d w1[e][d] * tags[tg][d] ============
__global__ void prep_kernel(const float* __restrict__ w1, const float* __restrict__ tags)
{
    int id = threadIdx.x;          // 256 threads
    int tg = id >> 6;
    int e = id & 63;
    float s = 0.f;
    for (int d = 0; d < 64; d++) s = fmaf(w1[e * 64 + d], tags[tg * 64 + d], s);
    g_tagw[tg * 64 + e] = s;
}

// ============ transformed conv weights: U = G g G^T, per layer ============
// stored interleaved for float4 GEMM loads: slot j*4+k holds co = k*8+j
__global__ void wtrans_kernel(const float* __restrict__ c2w, const float* __restrict__ c3w)
{
    int L = blockIdx.x;
    const float* wsrc = L ? c3w : c2w;
    for (int id = threadIdx.x; id < 1024; id += 256) {
        int ci = id & 31;
        int co = id >> 5;
        int slot = (co & 7) * 4 + (co >> 3);
        const float* g = wsrc + (co * 32 + ci) * 9;
        float tr[4][3];
        for (int j = 0; j < 3; j++) {
            float g0 = g[j], g1 = g[3 + j], g2 = g[6 + j];
            tr[0][j] = g0;
            tr[1][j] = 0.5f * (g0 + g1 + g2);
            tr[2][j] = 0.5f * (g0 - g1 + g2);
            tr[3][j] = g2;
        }
        for (int i = 0; i < 4; i++) {
            float t0 = tr[i][0], t1 = tr[i][1], t2 = tr[i][2];
            float u0 = t0;
            float u1 = 0.5f * (t0 + t1 + t2);
            float u2 = 0.5f * (t0 - t1 + t2);
            float u3 = t2;
            int base = ((L * 16 + i * 4) * 32 + ci) * 32 + slot;
            g_U[base]            = u0;
            g_U[base + 1 * 1024] = u1;
            g_U[base + 2 * 1024] = u2;
            g_U[base + 3 * 1024] = u3;
        }
    }
}

// ============ feature extractor: 1 image/block, 512 threads ============
__global__ __launch_bounds__(512, 2) void feat_kernel(
    const float* __restrict__ sxs, const float* __restrict__ qxs,
    const float* __restrict__ c1w, const float* __restrict__ c1b, const float* __restrict__ bn1,
    const float* __restrict__ c2b, const float* __restrict__ bn2,
    const float* __restrict__ c3b, const float* __restrict__ bn3,
    const float* __restrict__ c4w, const float* __restrict__ c4b, const float* __restrict__ bn4,
    const float* __restrict__ lin_w)
{
    extern __shared__ float sm[];
    float* Vs   = sm;           // 8192 (V, also conv1 scratch)
    float* bufA = sm + 8192;    // 3300
    float* bufB = sm + 11492;   // 3300
    float* w1s  = sm + 14792;   // 288
    float* w4s  = sm + 15080;   // 288
    float* A1 = sm + 15368; float* B1 = sm + 15400;
    float* A2 = sm + 15432; float* B2 = sm + 15464;
    float* A3 = sm + 15496; float* B3 = sm + 15528;
    float* AB4 = sm + 15560;
    float* flat = sm + 15568;
    float* red = sm + 15632;
    float* Ms = sm + 16144;     // 8704
    // total 24848 floats

    const int t = threadIdx.x;
    const int c = t & 31;
    const int g16 = t >> 5;
    const int img = blockIdx.x;
    const float* src = (img < 3072) ? (sxs + img * 784) : (qxs + (img - 3072) * 784);

    for (int i = t; i < 288; i += 512) {
        int co = i / 9; int k = i - co * 9;
        w1s[k * 32 + co] = c1w[i];
        w4s[i] = c4w[i];
    }
    if (t < 32) {
        float g = bn1[t], bt = bn1[32 + t], m = bn1[64 + t], v = bn1[96 + t];
        float sc = g * rsqrtf(v + 1e-5f);
        A1[t] = sc * 0.0625f;
        B1[t] = (c1b[t] - m) * sc + bt;
        g = bn2[t]; bt = bn2[32 + t]; m = bn2[64 + t]; v = bn2[96 + t];
        sc = g * rsqrtf(v + 1e-5f);
        A2[t] = sc; B2[t] = (c2b[t] - m) * sc + bt;
        g = bn3[t]; bt = bn3[32 + t]; m = bn3[64 + t]; v = bn3[96 + t];
        sc = g * rsqrtf(v + 1e-5f);
        A3[t] = sc; B3[t] = (c3b[t] - m) * sc + bt;
    }
    if (t == 0) {
        float g = bn4[0], bt = bn4[1], m = bn4[2], v = bn4[3];
        float sc = g * rsqrtf(v + 1e-5f);
        AB4[0] = sc; AB4[1] = (c4b[0] - m) * sc + bt;
    }
    for (int i = t; i < 3300; i += 512) { bufA[i] = 0.f; bufB[i] = 0.f; }

    float* inpad = Vs;
    float* rs4 = Vs + 1024;
    float* Ws = Vs + 2048;
    for (int i = t; i < 900; i += 512) {
        int yy = i / 30; int xx = i - yy * 30;
        float v = 0.f;
        if (yy >= 1 && yy <= 28 && xx >= 1 && xx <= 28) v = src[(yy - 1) * 28 + xx - 1];
        inpad[i] = v;
    }
    __syncthreads();
    {
        const int SO[8] = {0, 3, 7, 10, 14, 17, 21, 24};
        for (int i = t; i < 720; i += 512) {
            int u = i / 24; int b3 = i - u * 24;
            int b = SO[b3 / 3] + (b3 % 3);
            const float* ip = inpad + u * 30 + b;
            rs4[i] = ip[0] + ip[1] + ip[2] + ip[3];
        }
        __syncthreads();
        for (int i = t; i < 576; i += 512) {
            int a3 = i / 24; int b3 = i - a3 * 24;
            int a = SO[a3 / 3] + (a3 % 3);
            Ws[i] = rs4[a * 24 + b3] + rs4[(a + 1) * 24 + b3] + rs4[(a + 2) * 24 + b3] + rs4[(a + 3) * 24 + b3];
        }
        __syncthreads();
        int y = g16 >> 1;
        int x0 = (g16 & 1) * 4;
        float acc[4];
        for (int x = 0; x < 4; x++) acc[x] = 0.f;
        for (int dy = 0; dy < 3; dy++) for (int dx = 0; dx < 3; dx++) {
            float wv = w1s[(dy * 3 + dx) * 32 + c];
            for (int x = 0; x < 4; x++) acc[x] = fmaf(wv, Ws[(3 * y + dy) * 24 + 3 * (x0 + x) + dx], acc[x]);
        }
        float a1 = A1[c], b1 = B1[c];
        for (int x = 0; x < 4; x++) bufA[((y + 1) * 10 + x0 + x + 1) * 33 + c] = gelu_f(acc[x] * a1 + b1);
    }
    __syncthreads();

    for (int L = 0; L < 2; L++) {
        const float* inb = L ? bufB : bufA;
        float* outb = L ? bufA : bufB;
        const float* Asc = L ? A3 : A2;
        const float* Bof = L ? B3 : B2;

        {
            int tl = t & 15; int ci = t >> 4;
            int ty = tl >> 2; int tx = tl & 3;
            const float* base = inb + (2 * ty * 10 + 2 * tx) * 33 + ci;
            float d[4][4];
            for (int r = 0; r < 4; r++) for (int cc = 0; cc < 4; cc++) d[r][cc] = base[(r * 10 + cc) * 33];
            float tm[4][4];
            for (int j = 0; j < 4; j++) {
                tm[0][j] = d[0][j] - d[2][j];
                tm[1][j] = d[1][j] + d[2][j];
                tm[2][j] = d[2][j] - d[1][j];
                tm[3][j] = d[1][j] - d[3][j];
            }
            for (int i = 0; i < 4; i++) {
                Vs[(i * 4 + 0) * 512 + ci * 16 + tl] = tm[i][0] - tm[i][2];
                Vs[(i * 4 + 1) * 512 + ci * 16 + tl] = tm[i][1] + tm[i][2];
                Vs[(i * 4 + 2) * 512 + ci * 16 + tl] = tm[i][2] - tm[i][1];
                Vs[(i * 4 + 3) * 512 + ci * 16 + tl] = tm[i][1] - tm[i][3];
            }
        }
        __syncthreads();

        {
            int uv = g16;
            int q = c >> 3;
            int j = c & 7;
            float acc[16];
            for (int i = 0; i < 16; i++) acc[i] = 0.f;
            const float4* V4 = (const float4*)(Vs + uv * 512) + q;
            const float4* U4 = (const float4*)(g_U + (L * 16 + uv) * 1024) + j;
            #pragma unroll 8
            for (int ci = 0; ci < 32; ci++) {
                float4 v = V4[ci * 4];
                float4 u = U4[ci * 8];
                acc[0]  = fmaf(v.x, u.x, acc[0]);
                acc[1]  = fmaf(v.x, u.y, acc[1]);
                acc[2]  = fmaf(v.x, u.z, acc[2]);
                acc[3]  = fmaf(v.x, u.w, acc[3]);
                acc[4]  = fmaf(v.y, u.x, acc[4]);
                acc[5]  = fmaf(v.y, u.y, acc[5]);
                acc[6]  = fmaf(v.y, u.z, acc[6]);
                acc[7]  = fmaf(v.y, u.w, acc[7]);
                acc[8]  = fmaf(v.z, u.x, acc[8]);
                acc[9]  = fmaf(v.z, u.y, acc[9]);
                acc[10] = fmaf(v.z, u.z, acc[10]);
                acc[11] = fmaf(v.z, u.w, acc[11]);
                acc[12] = fmaf(v.w, u.x, acc[12]);
                acc[13] = fmaf(v.w, u.y, acc[13]);
                acc[14] = fmaf(v.w, u.z, acc[14]);
                acc[15] = fmaf(v.w, u.w, acc[15]);
            }
            float* Mw = Ms + uv * 544 + (q * 4) * 34 + j;
            for (int tlk = 0; tlk < 4; tlk++)
                for (int k = 0; k < 4; k++)
                    Mw[tlk * 34 + k * 8] = acc[tlk * 4 + k];
        }
        __syncthreads();

        {
            int co2 = t & 31; int tl = t >> 5;
            int ty = tl >> 2; int tx = tl & 3;
            float M[4][4];
            for (int i = 0; i < 4; i++) for (int j = 0; j < 4; j++) M[i][j] = Ms[(i * 4 + j) * 544 + tl * 34 + co2];
            float t0[2][4];
            for (int j = 0; j < 4; j++) {
                t0[0][j] = M[0][j] + M[1][j] + M[2][j];
                t0[1][j] = M[1][j] - M[2][j] - M[3][j];
            }
            float a = Asc[co2], bo = Bof[co2];
            for (int i = 0; i < 2; i++) {
                float y0 = t0[i][0] + t0[i][1] + t0[i][2];
                float y1 = t0[i][1] - t0[i][2] - t0[i][3];
                int rr = 1 + 2 * ty + i;
                int cc0 = 1 + 2 * tx;
                outb[(rr * 10 + cc0) * 33 + co2] = gelu_f(y0 * a + bo);
                outb[(rr * 10 + cc0 + 1) * 33 + co2] = gelu_f(y1 * a + bo);
            }
        }
        __syncthreads();
    }

    {
        int y = g16 >> 1;
        int x0 = (g16 & 1) * 4;
        float acc[4];
        for (int x = 0; x < 4; x++) acc[x] = 0.f;
        for (int dy = 0; dy < 3; dy++) for (int dx = 0; dx < 3; dx++) {
            float wv = w4s[c * 9 + dy * 3 + dx];
            const float* rp = bufA + ((y + dy) * 10 + x0 + dx) * 33 + c;
            for (int x = 0; x < 4; x++) acc[x] = fmaf(wv, rp[x * 33], acc[x]);
        }
        for (int x = 0; x < 4; x++) {
            float v = acc[x];
            for (int o = 16; o; o >>= 1) v += __shfl_xor_sync(0xffffffffu, v, o);
            if (c == 0) flat[y * 8 + x0 + x] = gelu_f(v * AB4[0] + AB4[1]);
        }
    }
    __syncthreads();

    {
        int e = t & 63;
        int h = t >> 6;
        int j0 = h * 8;
        float p = 0.f;
        for (int jj = 0; jj < 8; jj += 4) {
            float4 lw = *(const float4*)(lin_w + e * 64 + j0 + jj);
            p = fmaf(lw.x, flat[j0 + jj], p);
            p = fmaf(lw.y, flat[j0 + jj + 1], p);
            p = fmaf(lw.z, flat[j0 + jj + 2], p);
            p = fmaf(lw.w, flat[j0 + jj + 3], p);
        }
        red[h * 64 + e] = p;
        __syncthreads();
        if (t < 64) {
            float s = 0.f;
            for (int h2 = 0; h2 < 8; h2++) s += red[h2 * 64 + t];
            g_feats[img * 64 + t] = s;
        }
    }
}

// ============ LoR adapter: 16 tokens/block x 64 threads ============
__global__ __launch_bounds__(1024) void lor_kernel(
    const float* __restrict__ emb, const float* __restrict__ w1, const float* __restrict__ w2,
    const float* __restrict__ tags, const float* __restrict__ rq, const float* __restrict__ rk,
    const float* __restrict__ rv, const float* __restrict__ ro,
    const float* __restrict__ lnw, const float* __restrict__ lnb, const int* __restrict__ sys)
{
    extern __shared__ float sm[];
    float* w1T = sm;
    float* w2T = sm + 4160;
    float* rqT = sm + 8320;
    float* roS = sm + 12480;
    float* rkT = sm + 16576;
    float* rvS = sm + 17600;
    float* partS = sm + 18624;   // 1024 (first-GEMV partials)
    float* ahs = sm + 19648;
    float* qvs = sm + 20672;
    float* lvs = sm + 21696;
    float* rA = sm + 22720;
    float* rB = sm + 22752;
    float* bndS = sm + 22784;    // 256
    float* tgS = sm + 23040;     // 256
    float* tgwS = sm + 23296;    // 256 -> total 23552
    const int t = threadIdx.x;
    for (int i = t; i < 4096; i += 1024) {
        int e = i >> 6; int d = i & 63;
        w1T[d * 65 + e] = w1[i];
        w2T[d * 65 + e] = w2[i];
        rqT[d * 65 + e] = rq[i];
        roS[i] = ro[i];
    }
    {
        int n = t >> 8; int h = (t >> 4) & 15; int r = t & 15;
        rkT[t] = rk[(r * 4 + n) * 16 + h];
        rvS[t] = rv[t];
    }
    if (t < 256) {
        tgS[t] = tags[t];
        tgwS[t] = g_tagw[t];
    }
    const int lt = t >> 6;
    const int j = t & 63;
    const int tok = blockIdx.x * 16 + lt;
    const int b = tok / 24;
    const int k24 = tok - b * 24;
    const int s = k24 >> 2;
    const int tg = k24 & 3;
    const int g4 = lt >> 2;      // group within block (4 tokens share bound)
    if ((lt & 3) == 0) {
        int cls = sys[b * 6 + s];
        bndS[g4 * 64 + j] = g_feats[(b * 6 + s) * 64 + j] + emb[cls * 64 + j];
    }
    __syncthreads();
    {
        int p = lt & 3;
        float hp = 0.f;
        int d0 = p * 16;
        for (int dd = 0; dd < 16; dd++)
            hp = fmaf(w1T[(d0 + dd) * 65 + j], bndS[g4 * 64 + d0 + dd], hp);
        partS[t] = hp;
    }
    __syncthreads();
    float h1 = partS[(g4 * 4 + 0) * 64 + j] + partS[(g4 * 4 + 1) * 64 + j]
             + partS[(g4 * 4 + 2) * 64 + j] + partS[(g4 * 4 + 3) * 64 + j]
             + tgwS[tg * 64 + j];
    ahs[t] = gelu_f(h1);
    __syncthreads();
    float qv = 0.f;
    for (int d = 0; d < 64; d++) qv = fmaf(w2T[d * 65 + j], ahs[lt * 64 + d], qv);
    qvs[t] = qv;
    __syncthreads();
    float qh = 0.f;
    for (int d = 0; d < 64; d++) qh = fmaf(rqT[d * 65 + j], qvs[lt * 64 + d], qh);
    const int n = j >> 4;
    const int sub = j & 15;
    float scv = 0.f;
    for (int hh = 0; hh < 16; hh++) {
        float q2 = __shfl_sync(0xffffffffu, qh, hh, 16);
        scv = fmaf(q2, rkT[(n * 16 + hh) * 16 + sub], scv);
    }
    scv *= 0.25f;
    float mx = scv;
    for (int o = 8; o; o >>= 1) mx = fmaxf(mx, __shfl_xor_sync(0xffffffffu, mx, o, 16));
    float ee = expf(scv - mx);
    float ss = ee;
    for (int o = 8; o; o >>= 1) ss += __shfl_xor_sync(0xffffffffu, ss, o, 16);
    float p = ee / ss;
    float lv = 0.f;
    for (int r = 0; r < 16; r++) {
        float pr = __shfl_sync(0xffffffffu, p, r, 16);
        lv = fmaf(pr, rvS[(r * 4 + n) * 16 + sub], lv);
    }
    lvs[t] = lv;
    __syncthreads();
    float ov = 0.f;
    for (int d = 0; d < 64; d++) ov = fmaf(roS[d * 64 + j], lvs[lt * 64 + d], ov);
    float z = ov + bndS[g4 * 64 + j] + tgS[tg * 64 + j];
    float sv = z;
    for (int o = 16; o; o >>= 1) sv += __shfl_xor_sync(0xffffffffu, sv, o);
    int wh = j >> 5;
    if ((j & 31) == 0) rA[lt * 2 + wh] = sv;
    __syncthreads();
    float mean = (rA[lt * 2] + rA[lt * 2 + 1]) * 0.015625f;
    float dz = z - mean;
    float v2 = dz * dz;
    for (int o = 16; o; o >>= 1) v2 += __shfl_xor_sync(0xffffffffu, v2, o);
    if ((j & 31) == 0) rB[lt * 2 + wh] = v2;
    __syncthreads();
    float var = (rB[lt * 2] + rB[lt * 2 + 1]) * 0.015625f;
    g_lors[tok * 64 + j] = dz * rsqrtf(var + 1e-5f) * lnw[j] + lnb[j];
}

// ============ query path: 4 tasks/block, 256 threads, grid 128 ============
__global__ __launch_bounds__(256) void query_kernel(
    const float* __restrict__ emb, const float* __restrict__ w1, const float* __restrict__ w2,
    const float* __restrict__ tags, const int* __restrict__ qys)
{
    extern __shared__ float sm[];
    float* w1T = sm;
    float* w2T = sm + 4160;
    float* lorS = sm + 8320;
    float* xq = sm + 14464;
    float* ah = sm + 14976;
    float* pd = sm + 15488;
    float* d1 = sm + 16000;
    float* d2 = sm + 16048;
    float* lg = sm + 16096;
    float* ls = sm + 16112;
    float* cr = sm + 16120;
    const int t = threadIdx.x;
    for (int i = t; i < 4096; i += 256) {
        int e = i >> 6; int d = i & 63;
        w1T[d * 65 + e] = w1[i];
        w2T[d * 65 + e] = w2[i];
    }
    for (int i = t; i < 6144; i += 256) lorS[i] = g_lors[blockIdx.x * 6144 + i];
    const int bl = t >> 6;
    const int e = t & 63;
    const int b = blockIdx.x * 4 + bl;
    for (int q = 0; q < 2; q++) xq[(bl * 2 + q) * 64 + e] = g_feats[3072 * 64 + (b * 2 + q) * 64 + e] + tags[4 * 64 + e];
    __syncthreads();
    if (e < 12) {
        int s = e >> 1; int q = e & 1;
        const float* r1 = lorS + bl * 1536 + (s * 4 + 1) * 64;
        const float* xx = xq + (bl * 2 + q) * 64;
        float a = 0.f;
        for (int d = 0; d < 64; d++) a = fmaf(r1[d], xx[d], a);
        d1[bl * 12 + e] = a;
    }
    __syncthreads();
    for (int q = 0; q < 2; q++) {
        const float* xx = xq + (bl * 2 + q) * 64;
        float a = 0.f;
        for (int d = 0; d < 64; d++) a = fmaf(w1T[d * 65 + e], xx[d], a);
        for (int s = 0; s < 6; s++) a = fmaf(lorS[bl * 1536 + (s * 4) * 64 + e], d1[bl * 12 + s * 2 + q], a);
        ah[(bl * 2 + q) * 64 + e] = gelu_f(a);
    }
    __syncthreads();
    if (e < 12) {
        int s = e >> 1; int q = e & 1;
        const float* r2 = lorS + bl * 1536 + (s * 4 + 3) * 64;
        const float* aa = ah + (bl * 2 + q) * 64;
        float a = 0.f;
        for (int d = 0; d < 64; d++) a = fmaf(r2[d], aa[d], a);
        d2[bl * 12 + e] = a;
    }
    __syncthreads();
    for (int q = 0; q < 2; q++) {
        const float* aa = ah + (bl * 2 + q) * 64;
        float a = 0.f;
        for (int d = 0; d < 64; d++) a = fmaf(w2T[d * 65 + e], aa[d], a);
        for (int s = 0; s < 6; s++) a = fmaf(lorS[bl * 1536 + (s * 4 + 2) * 64 + e], d2[bl * 12 + s * 2 + q], a);
        pd[(bl * 2 + q) * 64 + e] = a;
    }
    __syncthreads();
    if (e < 4) {
        int q = e >> 1; int l = e & 1;
        float a = 0.f;
        for (int d = 0; d < 64; d++) a = fmaf(emb[l * 64 + d], pd[(bl * 2 + q) * 64 + d], a);
        lg[bl * 4 + e] = a;
    }
    __syncthreads();
    if (e < 2) {
        float l0 = lg[bl * 4 + e * 2];
        float l1 = lg[bl * 4 + e * 2 + 1];
        int yv = qys[b * 2 + e];
        float m = fmaxf(l0, l1);
        float lse = m + logf(expf(l0 - m) + expf(l1 - m));
        ls[bl * 2 + e] = lse - (yv ? l1 : l0);
        cr[bl * 2 + e] = (((l1 > l0) ? 1 : 0) == yv) ? 1.f : 0.f;
    }
    __syncthreads();
    if (t == 0) {
        float sl = 0.f;
        float sc = 0.f;
        for (int i = 0; i < 8; i++) { sl += ls[i]; sc += cr[i]; }
        g_ploss[blockIdx.x] = sl;
        g_pcorr[blockIdx.x] = sc;
    }
}

__global__ void reduce_kernel(float* __restrict__ out)
{
    __shared__ float sl[128];
    __shared__ float sc[128];
    int t = threadIdx.x;
    sl[t] = g_ploss[t];
    sc[t] = g_pcorr[t];
    __syncthreads();
    for (int s = 64; s; s >>= 1) {
        if (t < s) { sl[t] += sl[t + s]; sc[t] += sc[t + s]; }
        __syncthreads();
    }
    if (t == 0) {
        float loss = sl[0] * 0.0009765625f;
        out[0] = loss;
        out[1] = loss;
        out[2] = 0.f;
        out[3] = sc[0];
        out[4] = 1024.f;
    }
}

extern "C" void kernel_launch(void* const* d_in, const int* in_sizes, int n_in,
                              void* d_out, int out_size)
{
    const float* sxs = (const float*)d_in[1];
    const float* qxs = (const float*)d_in[2];
    const float* c1w = (const float*)d_in[4];
    const float* c1b = (const float*)d_in[5];
    const float* bn1 = (const float*)d_in[6];
    const float* c2w = (const float*)d_in[7];
    const float* c2b = (const float*)d_in[8];
    const float* bn2 = (const float*)d_in[9];
    const float* c3w = (const float*)d_in[10];
    const float* c3b = (const float*)d_in[11];
    const float* bn3 = (const float*)d_in[12];
    const float* c4w = (const float*)d_in[13];
    const float* c4b = (const float*)d_in[14];
    const float* bn4 = (const float*)d_in[15];
    const float* lin_w = (const float*)d_in[16];
    const float* emb = (const float*)d_in[17];
    const float* w1 = (const float*)d_in[18];
    const float* w2 = (const float*)d_in[19];
    const float* tags = (const float*)d_in[20];
    const float* rq = (const float*)d_in[21];
    const float* rk = (const float*)d_in[22];
    const float* rv = (const float*)d_in[23];
    const float* ro = (const float*)d_in[24];
    const float* lnw = (const float*)d_in[25];
    const float* lnb = (const float*)d_in[26];
    const int* sys = (const int*)d_in[27];
    const int* qys = (const int*)d_in[28];
    const size_t smF = 24848 * sizeof(float);
    const size_t smL = 23552 * sizeof(float);
    const size_t smQ = 16128 * sizeof(float);
    cudaFuncSetAttribute(feat_kernel, cudaFuncAttributeMaxDynamicSharedMemorySize, (int)smF);
    cudaFuncSetAttribute(lor_kernel, cudaFuncAttributeMaxDynamicSharedMemorySize, (int)smL);
    cudaFuncSetAttribute(query_kernel, cudaFuncAttributeMaxDynamicSharedMemorySize, (int)smQ);
    // lor_kernel sits at 0-based position 3 (ncu capture slot)
    wtrans_kernel<<<2, 256>>>(c2w, c3w);
    prep_kernel<<<1, 256>>>(w1, tags);
    feat_kernel<<<4096, 512, smF>>>(sxs, qxs, c1w, c1b, bn1, c2b, bn2, c3b, bn3, c4w, c4b, bn4, lin_w);
    lor_kernel<<<768, 1024, smL>>>(emb, w1, w2, tags, rq, rk, rv, ro, lnw, lnb, sys);
    query_kernel<<<128, 256, smQ>>>(emb, w1, w2, tags, qys);
    reduce_kernel<<<1, 128>>>((float*)d_out);
}